// round 15
// baseline (speedup 1.0000x reference)
#include <cuda_runtime.h>

// ReduceBoundingBoxes: ONE kernel, 9 blocks.
//   blocks 1..8 (helpers): zero out (1 float4/thread), block 1 also prefetches
//     x to L2; signal d_zdone and exit.
//   block 0 (worker): 8-pixel/thread pass (hist + per-warp segment append +
//     L1-prefetch of the valid pixels' channel lines) -> prefix sum over 2048
//     buckets -> [poll zero-flag] -> S4: singles (count==1) gather+write rows
//     directly, collisions -> scat+cidx -> S5: resolve ~200 collisions ->
//     nd-list build -> warp-0 greedy NMS.
// x: (5, 80, 80) f32 channel-major. out: (6400, 5) f32.
//
// key = (u64(~bits(score)) << 32) | idx ; ascending == (score desc, idx asc).
// Valid scores s in (0.9, 1.0) share exponent 126 -> u = ~bits(s) lies in
// (0xC0800000, 0xC099999A); bucket = clamp((u - 0xC0800000) >> 10, 0, 2047)
// is monotone in u. Out-of-range scores clamp into end buckets, resolved by
// exact u64 compares -> correct for any input.

#define NPIX 6400
#define NT   1024
#define NB   2048
#define NZB  8              // helper (zeroing) blocks
#define SEG  256            // max valid pixels per warp (8/thread * 32)

__device__ int d_zdone;     // zero-init; block 0 resets at end of each run

// dynamic smem layout (bytes), block 0 only:
//   [0,      65536)  u64 klist[32][256]  (per-warp valid-key segments)
//                    reused as int ndlist[6400] after S4
//   [65536,  73728)  int cursor[2048]    (hist -> running offsets)
//                    reused as u8 kb[6400]... NO: kb gets its own slice below
//   [73728,  81936)  int base0[2049] (+pad)
//   [81936, 133136)  u64 scat[6400]      (collision keys, bucket-ordered)
//   [133136,145936)  u16 cidx[6400]      (collision slot list)
//   [145936,152336)  u8 ndflag[6400]
//   kb[6400] aliases cursor+cidx? -> kb aliases cidx after S5 is done? cidx
//   read in S5, kb written in S6b; S6b runs after S5 barrier -> alias OK.
#define KLIST_OFF  0
#define CUR_OFF    65536
#define BASE_OFF   73728
#define SCAT_OFF   81936
#define CIDX_OFF   133136
#define NDFLAG_OFF 145936
#define SMEM_BYTES 152336

__device__ __forceinline__ int bucket_of(unsigned u) {
    unsigned d = u - 0xC0800000u;
    int b = (u < 0xC0800000u) ? 0 : (int)(d >> 10);
    return b > (NB - 1) ? (NB - 1) : b;
}

__global__ void __launch_bounds__(NT, 1)
bb_kernel(const float* __restrict__ x, float* __restrict__ out) {
    const int tid  = threadIdx.x;
    const int lane = tid & 31;
    const int wid  = tid >> 5;

    // ================= helper blocks: zero out + prefetch =================
    if (blockIdx.x != 0) {
        int zb = blockIdx.x - 1;
        if (zb == 0 && tid < 1000) {   // prefetch x: 128000 B = 1000 lines
            const char* p = (const char*)x + tid * 128;
            asm volatile("prefetch.global.L2 [%0];" :: "l"(p));
        }
        int gi = zb * NT + tid;        // 8 * 1024 = 8192 >= 8000 float4
        if (gi < (NPIX * 5) / 4)
            ((float4*)out)[gi] = make_float4(0.f, 0.f, 0.f, 0.f);
        __threadfence();               // release: zeros visible device-wide
        __syncthreads();
        if (tid == 0) atomicAdd(&d_zdone, 1);
        return;
    }

    // ======================== worker block 0 ==============================
    extern __shared__ unsigned char smem[];
    unsigned long long* klist  = (unsigned long long*)(smem + KLIST_OFF);
    int*                ndlist = (int*)(smem + KLIST_OFF);  // reuse after S4
    int*                cursor = (int*)(smem + CUR_OFF);
    int*                base0  = (int*)(smem + BASE_OFF);
    unsigned long long* scat   = (unsigned long long*)(smem + SCAT_OFF);
    unsigned short*     cidx   = (unsigned short*)(smem + CIDX_OFF);
    unsigned char*      kb     = smem + CIDX_OFF;           // reuse after S5
    unsigned char*      ndflag = smem + NDFLAG_OFF;
    __shared__ int wsum[32];
    __shared__ int wcnt[32];
    __shared__ int sG;
    __shared__ int sC;

    // ---- S1: issue ch0 loads FIRST (overlap), then zero histogram ----
    const bool hasb = (tid + NT) < (NPIX / 4);   // 1600 float4 total
    float4 sa = ((const float4*)x)[tid];
    float4 sb = make_float4(0.f, 0.f, 0.f, 0.f);
    if (hasb) sb = ((const float4*)x)[tid + NT];
    ((int2*)cursor)[tid] = make_int2(0, 0);      // 2048 ints, 2/thread
    if (tid == 0) sC = 0;
    __syncthreads();

    // ---- S2: 8 pixels/thread: hist + L1 prefetch + segment append ----
    float sv[8] = {sa.x, sa.y, sa.z, sa.w, sb.x, sb.y, sb.z, sb.w};
    unsigned uu[8];
    int vm = 0, cnt = 0;
    #pragma unroll
    for (int e = 0; e < 8; e++) {
        if (sv[e] > 0.9f) {
            uu[e] = ~__float_as_uint(sv[e]);
            vm |= 1 << e;
            cnt++;
            atomicAdd(&cursor[bucket_of(uu[e])], 1);
            // L1-prefetch this pixel's 4 channel values for S4's gather
            unsigned pix = (e < 4) ? (unsigned)(tid * 4 + e)
                                   : (unsigned)((tid + NT) * 4 + e - 4);
            const char* pc = (const char*)(x + NPIX + pix);
            asm volatile("prefetch.global.L1 [%0];" :: "l"(pc));
            asm volatile("prefetch.global.L1 [%0];" :: "l"(pc + NPIX * 4));
            asm volatile("prefetch.global.L1 [%0];" :: "l"(pc + NPIX * 8));
            asm volatile("prefetch.global.L1 [%0];" :: "l"(pc + NPIX * 12));
        }
    }
    int inc = cnt;                     // warp inclusive scan of cnt
    #pragma unroll
    for (int j = 1; j < 32; j <<= 1) {
        int n = __shfl_up_sync(0xffffffffu, inc, j);
        if (lane >= j) inc += n;
    }
    {
        int base = inc - cnt;
        int k = 0;
        #pragma unroll
        for (int e = 0; e < 8; e++) {
            if (vm & (1 << e)) {
                unsigned pix = (e < 4) ? (unsigned)(tid * 4 + e)
                                       : (unsigned)((tid + NT) * 4 + e - 4);
                klist[wid * SEG + base + k] =
                    (((unsigned long long)uu[e]) << 32) | pix;
                k++;
            }
        }
    }
    const int mycnt = __shfl_sync(0xffffffffu, inc, 31);  // warp total
    __syncthreads();

    // ---- S3: exclusive prefix sum over 2048 buckets (int2, 2/thread) ----
    int2 c2 = ((int2*)cursor)[tid];
    int local = c2.x + c2.y;
    int v = local;
    #pragma unroll
    for (int j = 1; j < 32; j <<= 1) {
        int n = __shfl_up_sync(0xffffffffu, v, j);
        if (lane >= j) v += n;
    }
    if (lane == 31) wsum[wid] = v;
    __syncthreads();
    if (wid == 0) {
        int w = wsum[lane];
        #pragma unroll
        for (int j = 1; j < 32; j <<= 1) {
            int n = __shfl_up_sync(0xffffffffu, w, j);
            if (lane >= j) w += n;
        }
        wsum[lane] = w;
    }
    __syncthreads();
    int ex = v - local + (wid ? wsum[wid - 1] : 0);
    ((int2*)base0)[tid]  = make_int2(ex, ex + c2.x);
    ((int2*)cursor)[tid] = make_int2(ex, ex + c2.x);
    const int M = wsum[31];
    if (tid == 0) base0[NB] = M;

    // ---- poll zero-done flag (S4 writes rows, needs zeros ordered) ----
    if (tid == 0)
        while (atomicAdd(&d_zdone, 0) < NZB) { }
    __syncthreads();
    __threadfence();   // acquire: helpers' zeros ordered before our writes

    if (M > 0) {
        // ---- S4: singles -> gather+write row now; collisions -> scat ----
        // b5 = (f0, f1, f0+f2, f1+f3, f4); box = (f1, f0+f2, f1+f3, f4)
        for (int p = lane; p < mycnt; p += 32) {
            unsigned long long key = klist[wid * SEG + p];
            unsigned u = (unsigned)(key >> 32);
            int b = bucket_of(u);
            int s0 = base0[b], e0 = base0[b + 1];
            if (e0 - s0 == 1) {
                int r = s0;
                unsigned i = (unsigned)key;
                float f0 = __uint_as_float(~u);
                float f1 = x[NPIX + i];       // L1-warm (prefetched in S2)
                float f2 = x[2 * NPIX + i];
                float f3 = x[3 * NPIX + i];
                float f4 = x[4 * NPIX + i];
                float cc2 = f0 + f2;
                float cc3 = f1 + f3;
                out[r * 5 + 0] = f0;
                out[r * 5 + 1] = f1;
                out[r * 5 + 2] = cc2;
                out[r * 5 + 3] = cc3;
                out[r * 5 + 4] = f4;
                ndflag[r] = ((cc3 - f1) > 0.f && (f4 - cc2) > 0.f) ? 1 : 0;
            } else {
                int slot = atomicAdd(&cursor[b], 1);
                scat[slot] = key;
                cidx[atomicAdd(&sC, 1)] = (unsigned short)slot;
            }
        }
        __syncthreads();   // klist dead -> ndlist reuse OK
        const int C = sC;

        // ---- S5: resolve collision ranks (~200 elems) + gather+write ----
        for (int c = tid; c < C; c += NT) {
            int slot = cidx[c];
            unsigned long long key = scat[slot];
            unsigned u = (unsigned)(key >> 32);
            int b = bucket_of(u);
            int s0 = base0[b], e0 = base0[b + 1];
            int r = s0;
            for (int q = s0; q < e0; q++) r += (scat[q] < key);

            unsigned i = (unsigned)key;
            float f0 = __uint_as_float(~u);
            float f1 = x[NPIX + i];           // L1-warm
            float f2 = x[2 * NPIX + i];
            float f3 = x[3 * NPIX + i];
            float f4 = x[4 * NPIX + i];
            float cc2 = f0 + f2;
            float cc3 = f1 + f3;
            out[r * 5 + 0] = f0;
            out[r * 5 + 1] = f1;
            out[r * 5 + 2] = cc2;
            out[r * 5 + 3] = cc3;
            out[r * 5 + 4] = f4;
            ndflag[r] = ((cc3 - f1) > 0.f && (f4 - cc2) > 0.f) ? 1 : 0;
        }
        __syncthreads();   // cidx dead -> kb reuse OK

        // ---- S6a: order-preserving non-degenerate list build ----
        int g;
        if (M <= NT) {
            int r = wid * 32 + lane;
            bool f = (r < M) && (ndflag[r] != 0);
            unsigned mybal = __ballot_sync(0xffffffffu, f);
            if (lane == 0) wcnt[wid] = __popc(mybal);
            __syncthreads();
            if (tid < 32) {
                int c = wcnt[lane];
                int p = c;
                #pragma unroll
                for (int j = 1; j < 32; j <<= 1) {
                    int n = __shfl_up_sync(0xffffffffu, p, j);
                    if (lane >= j) p += n;
                }
                wcnt[lane] = p - c;           // exclusive offsets
                if (lane == 31) sG = p;
            }
            __syncthreads();
            if (f) ndlist[wcnt[wid] + __popc(mybal & ((1u << lane) - 1u))] = r;
            __syncthreads();
            g = sG;
        } else {
            // fallback (M > 1024; ~never): warp-0 sequential build
            if (tid < 32) {
                int gg = 0;
                for (int base = 0; base < M; base += 32) {
                    int r = base + lane;
                    bool f = (r < M) && (ndflag[r] != 0);
                    unsigned bal = __ballot_sync(0xffffffffu, f);
                    if (f)
                        ndlist[gg + __popc(bal & ((1u << lane) - 1u))] = r;
                    gg += __popc(bal);
                }
                if (lane == 0) sG = gg;
            }
            __syncthreads();
            g = sG;
        }

        // ---- S6b: warp 0 — greedy NMS over non-degenerate boxes ----
        // degenerate boxes (w<=0 or h<=0) have IoU 0 with everything:
        // never suppressed, never suppress -> rows stay as written.
        if (tid < 32) {
            for (int i2 = 0; i2 < g; i2++) {
                int ri = ndlist[i2];
                float ax0 = out[ri * 5 + 1], ay0 = out[ri * 5 + 2];
                float ax1 = out[ri * 5 + 3], ay1 = out[ri * 5 + 4];
                float aarea = fmaxf(ax1 - ax0, 0.f) * fmaxf(ay1 - ay0, 0.f);
                bool sup = false;
                for (int j = lane; j < i2; j += 32) {
                    if (kb[j]) {
                        int rj = ndlist[j];
                        float bx0 = out[rj * 5 + 1], by0 = out[rj * 5 + 2];
                        float bx1 = out[rj * 5 + 3], by1 = out[rj * 5 + 4];
                        float barea = fmaxf(bx1 - bx0, 0.f) *
                                      fmaxf(by1 - by0, 0.f);
                        float iw = fminf(ax1, bx1) - fmaxf(ax0, bx0);
                        float ih = fminf(ay1, by1) - fmaxf(ay0, by0);
                        float inter = fmaxf(iw, 0.f) * fmaxf(ih, 0.f);
                        float uni = aarea + barea - inter;
                        if (inter / fmaxf(uni, 1e-9f) > 0.5f) sup = true;
                    }
                }
                sup = __any_sync(0xffffffffu, sup);
                if (lane == 0) {
                    kb[i2] = sup ? 0 : 1;
                    if (sup) {   // suppressed row -> zeros
                        out[ri * 5 + 0] = 0.f;
                        out[ri * 5 + 1] = 0.f;
                        out[ri * 5 + 2] = 0.f;
                        out[ri * 5 + 3] = 0.f;
                        out[ri * 5 + 4] = 0.f;
                    }
                }
                __syncwarp();
            }
        }
    }

    // ---- reset flag for next graph replay ----
    __syncthreads();
    if (tid == 0) d_zdone = 0;
}

extern "C" void kernel_launch(void* const* d_in, const int* in_sizes, int n_in,
                              void* d_out, int out_size) {
    const float* x = (const float*)d_in[0];
    float* out = (float*)d_out;
    cudaFuncSetAttribute(bb_kernel,
                         cudaFuncAttributeMaxDynamicSharedMemorySize,
                         SMEM_BYTES);
    bb_kernel<<<NZB + 1, NT, SMEM_BYTES>>>(x, out);
}

// round 16
// speedup vs baseline: 1.2710x; 1.2710x over previous
#include <cuda_runtime.h>

// ReduceBoundingBoxes: ONE kernel, 9 blocks. (R13 structure.)
//   blocks 1..8 (helpers): zero out (1 float4/thread), block 1 also prefetches
//     x to L2; signal d_zdone and exit.
//   block 0 (worker): 8-pixel/thread pass (hist + per-warp segment append,
//     ONE warp scan) -> prefix sum -> [poll zero-flag] -> per-warp scatter ->
//     rank+gather+write rows (loads hoisted) -> nd-list build -> warp-0 NMS.
// x: (5, 80, 80) f32 channel-major. out: (6400, 5) f32.
//
// key = (u64(~bits(score)) << 32) | idx ; ascending == (score desc, idx asc).
// Valid scores s in (0.9, 1.0) share exponent 126 -> u = ~bits(s) lies in
// (0xC0800000, 0xC099999A); bucket = clamp((u - 0xC0800000) >> 9, 0, 4095)
// is monotone in u. Out-of-range scores clamp into end buckets, resolved by
// exact u64 compares -> correct for any input.

#define NPIX 6400
#define NT   1024
#define NB   4096
#define NZB  8              // helper (zeroing) blocks
#define SEG  256            // max valid pixels per warp (8/thread * 32)

__device__ int d_zdone;     // zero-init; block 0 resets at end of each run

// dynamic smem layout (bytes), block 0 only:
//   [0,      65536)  u64 klist[32][256]  (per-warp valid-key segments)
//                    reused as int ndlist[6400] after S4
//   [65536,  81920)  int cursor[4096]    (hist -> running offsets)
//                    reused as u8 kb[6400] after S4
//   [81920,  98432)  int base0[4097] (+pad)
//   [98432, 149632)  u64 scat[6400]      (keys, bucket-ordered)
//   [149632,156032)  u8 ndflag[6400]
#define KLIST_OFF  0
#define CUR_OFF    65536
#define BASE_OFF   81920
#define SCAT_OFF   98432
#define NDFLAG_OFF 149632
#define SMEM_BYTES 156032

__device__ __forceinline__ int bucket_of(unsigned u) {
    unsigned d = u - 0xC0800000u;
    int b = (u < 0xC0800000u) ? 0 : (int)(d >> 9);
    return b > (NB - 1) ? (NB - 1) : b;
}

__global__ void __launch_bounds__(NT, 1)
bb_kernel(const float* __restrict__ x, float* __restrict__ out) {
    const int tid  = threadIdx.x;
    const int lane = tid & 31;
    const int wid  = tid >> 5;

    // ================= helper blocks: zero out + prefetch =================
    if (blockIdx.x != 0) {
        int zb = blockIdx.x - 1;
        if (zb == 0 && tid < 1000) {   // prefetch x: 128000 B = 1000 lines
            const char* p = (const char*)x + tid * 128;
            asm volatile("prefetch.global.L2 [%0];" :: "l"(p));
        }
        int gi = zb * NT + tid;        // 8 * 1024 = 8192 >= 8000 float4
        if (gi < (NPIX * 5) / 4)
            ((float4*)out)[gi] = make_float4(0.f, 0.f, 0.f, 0.f);
        __threadfence();               // release: zeros visible device-wide
        __syncthreads();
        if (tid == 0) atomicAdd(&d_zdone, 1);
        return;
    }

    // ======================== worker block 0 ==============================
    extern __shared__ unsigned char smem[];
    unsigned long long* klist  = (unsigned long long*)(smem + KLIST_OFF);
    int*                ndlist = (int*)(smem + KLIST_OFF);  // reuse after S4
    int*                cursor = (int*)(smem + CUR_OFF);
    unsigned char*      kb     = smem + CUR_OFF;            // reuse after S4
    int*                base0  = (int*)(smem + BASE_OFF);
    unsigned long long* scat   = (unsigned long long*)(smem + SCAT_OFF);
    unsigned char*      ndflag = smem + NDFLAG_OFF;
    __shared__ int wsum[32];
    __shared__ int wcnt[32];
    __shared__ int sG;

    // ---- S1: issue ch0 loads FIRST (overlap), then zero histogram ----
    const bool hasb = (tid + NT) < (NPIX / 4);   // 1600 float4 total
    float4 sa = ((const float4*)x)[tid];
    float4 sb = make_float4(0.f, 0.f, 0.f, 0.f);
    if (hasb) sb = ((const float4*)x)[tid + NT];
    ((int4*)cursor)[tid] = make_int4(0, 0, 0, 0);   // 4096 ints, 4/thread
    __syncthreads();

    // ---- S2: 8 pixels/thread: hist + per-warp segment append, 1 scan ----
    float sv[8] = {sa.x, sa.y, sa.z, sa.w, sb.x, sb.y, sb.z, sb.w};
    unsigned uu[8];
    int vm = 0, cnt = 0;
    #pragma unroll
    for (int e = 0; e < 8; e++) {
        if (sv[e] > 0.9f) {
            uu[e] = ~__float_as_uint(sv[e]);
            vm |= 1 << e;
            cnt++;
            atomicAdd(&cursor[bucket_of(uu[e])], 1);
        }
    }
    int inc = cnt;                     // warp inclusive scan of cnt
    #pragma unroll
    for (int j = 1; j < 32; j <<= 1) {
        int n = __shfl_up_sync(0xffffffffu, inc, j);
        if (lane >= j) inc += n;
    }
    {
        int base = inc - cnt;
        int k = 0;
        #pragma unroll
        for (int e = 0; e < 8; e++) {
            if (vm & (1 << e)) {
                unsigned pix = (e < 4) ? (unsigned)(tid * 4 + e)
                                       : (unsigned)((tid + NT) * 4 + e - 4);
                klist[wid * SEG + base + k] =
                    (((unsigned long long)uu[e]) << 32) | pix;
                k++;
            }
        }
    }
    const int mycnt = __shfl_sync(0xffffffffu, inc, 31);  // warp total
    __syncthreads();

    // ---- S3: exclusive prefix sum over 4096 buckets (int4, 4/thread) ----
    int4 c4 = ((int4*)cursor)[tid];
    int local = c4.x + c4.y + c4.z + c4.w;
    int v = local;
    #pragma unroll
    for (int j = 1; j < 32; j <<= 1) {
        int n = __shfl_up_sync(0xffffffffu, v, j);
        if (lane >= j) v += n;
    }
    if (lane == 31) wsum[wid] = v;
    __syncthreads();
    if (wid == 0) {
        int w = wsum[lane];
        #pragma unroll
        for (int j = 1; j < 32; j <<= 1) {
            int n = __shfl_up_sync(0xffffffffu, w, j);
            if (lane >= j) w += n;
        }
        wsum[lane] = w;
    }
    __syncthreads();
    int ex = v - local + (wid ? wsum[wid - 1] : 0);
    int4 b4 = make_int4(ex, ex + c4.x, ex + c4.x + c4.y,
                        ex + c4.x + c4.y + c4.z);
    ((int4*)base0)[tid]  = b4;
    ((int4*)cursor)[tid] = b4;
    const int M = wsum[31];
    if (tid == 0) base0[NB] = M;

    // ---- poll zero-done flag, acquire helpers' zeros ----
    if (tid == 0)
        while (atomicAdd(&d_zdone, 0) < NZB) { }
    __syncthreads();
    __threadfence();   // acquire: helpers' zeros ordered before row writes

    if (M > 0) {
        // ---- S4: each warp scatters its own segment (~20 elems) ----
        for (int p = lane; p < mycnt; p += 32) {
            unsigned long long key = klist[wid * SEG + p];
            int b = bucket_of((unsigned)(key >> 32));
            scat[atomicAdd(&cursor[b], 1)] = key;
        }
        __syncthreads();   // klist/cursor dead -> ndlist/kb reuse OK

        // ---- S5: rank + gather (loads hoisted) + write rows ----
        // b5 = (f0, f1, f0+f2, f1+f3, f4); box = (f1, f0+f2, f1+f3, f4)
        for (int p = tid; p < M; p += NT) {
            unsigned long long key = scat[p];
            unsigned u = (unsigned)(key >> 32);
            unsigned i = (unsigned)key;
            // issue all channel loads up front (overlap with rank loop)
            float f1 = __ldg(&x[NPIX + i]);
            float f2 = __ldg(&x[2 * NPIX + i]);
            float f3 = __ldg(&x[3 * NPIX + i]);
            float f4 = __ldg(&x[4 * NPIX + i]);

            int b = bucket_of(u);
            int s0 = base0[b], e0 = base0[b + 1];
            int r = s0;
            if (e0 - s0 > 1)
                for (int q = s0; q < e0; q++) r += (scat[q] < key);

            float f0 = __uint_as_float(~u);
            float cc2 = f0 + f2;
            float cc3 = f1 + f3;
            out[r * 5 + 0] = f0;
            out[r * 5 + 1] = f1;
            out[r * 5 + 2] = cc2;
            out[r * 5 + 3] = cc3;
            out[r * 5 + 4] = f4;
            ndflag[r] = ((cc3 - f1) > 0.f && (f4 - cc2) > 0.f) ? 1 : 0;
        }
        __syncthreads();

        // ---- S6a: order-preserving non-degenerate list build ----
        int g;
        if (M <= NT) {
            int r = wid * 32 + lane;
            bool f = (r < M) && (ndflag[r] != 0);
            unsigned mybal = __ballot_sync(0xffffffffu, f);
            if (lane == 0) wcnt[wid] = __popc(mybal);
            __syncthreads();
            if (tid < 32) {
                int c = wcnt[lane];
                int p = c;
                #pragma unroll
                for (int j = 1; j < 32; j <<= 1) {
                    int n = __shfl_up_sync(0xffffffffu, p, j);
                    if (lane >= j) p += n;
                }
                wcnt[lane] = p - c;           // exclusive offsets
                if (lane == 31) sG = p;
            }
            __syncthreads();
            if (f) ndlist[wcnt[wid] + __popc(mybal & ((1u << lane) - 1u))] = r;
            __syncthreads();
            g = sG;
        } else {
            // fallback (M > 1024; ~never): warp-0 sequential build
            if (tid < 32) {
                int gg = 0;
                for (int base = 0; base < M; base += 32) {
                    int r = base + lane;
                    bool f = (r < M) && (ndflag[r] != 0);
                    unsigned bal = __ballot_sync(0xffffffffu, f);
                    if (f)
                        ndlist[gg + __popc(bal & ((1u << lane) - 1u))] = r;
                    gg += __popc(bal);
                }
                if (lane == 0) sG = gg;
            }
            __syncthreads();
            g = sG;
        }

        // ---- S6b: warp 0 — greedy NMS over non-degenerate boxes ----
        // degenerate boxes (w<=0 or h<=0) have IoU 0 with everything:
        // never suppressed, never suppress -> rows stay as written.
        if (tid < 32) {
            for (int i2 = 0; i2 < g; i2++) {
                int ri = ndlist[i2];
                float ax0 = out[ri * 5 + 1], ay0 = out[ri * 5 + 2];
                float ax1 = out[ri * 5 + 3], ay1 = out[ri * 5 + 4];
                float aarea = fmaxf(ax1 - ax0, 0.f) * fmaxf(ay1 - ay0, 0.f);
                bool sup = false;
                for (int j = lane; j < i2; j += 32) {
                    if (kb[j]) {
                        int rj = ndlist[j];
                        float bx0 = out[rj * 5 + 1], by0 = out[rj * 5 + 2];
                        float bx1 = out[rj * 5 + 3], by1 = out[rj * 5 + 4];
                        float barea = fmaxf(bx1 - bx0, 0.f) *
                                      fmaxf(by1 - by0, 0.f);
                        float iw = fminf(ax1, bx1) - fmaxf(ax0, bx0);
                        float ih = fminf(ay1, by1) - fmaxf(ay0, by0);
                        float inter = fmaxf(iw, 0.f) * fmaxf(ih, 0.f);
                        float uni = aarea + barea - inter;
                        if (inter / fmaxf(uni, 1e-9f) > 0.5f) sup = true;
                    }
                }
                sup = __any_sync(0xffffffffu, sup);
                if (lane == 0) {
                    kb[i2] = sup ? 0 : 1;
                    if (sup) {   // suppressed row -> zeros
                        out[ri * 5 + 0] = 0.f;
                        out[ri * 5 + 1] = 0.f;
                        out[ri * 5 + 2] = 0.f;
                        out[ri * 5 + 3] = 0.f;
                        out[ri * 5 + 4] = 0.f;
                    }
                }
                __syncwarp();
            }
        }
    }

    // ---- reset flag for next graph replay ----
    __syncthreads();
    if (tid == 0) d_zdone = 0;
}

extern "C" void kernel_launch(void* const* d_in, const int* in_sizes, int n_in,
                              void* d_out, int out_size) {
    const float* x = (const float*)d_in[0];
    float* out = (float*)d_out;
    cudaFuncSetAttribute(bb_kernel,
                         cudaFuncAttributeMaxDynamicSharedMemorySize,
                         SMEM_BYTES);
    bb_kernel<<<NZB + 1, NT, SMEM_BYTES>>>(x, out);
}